// round 7
// baseline (speedup 1.0000x reference)
#include <cuda_runtime.h>
#include <cuda_bf16.h>

#define RDIM 256
#define SDIM 256

// Scan + scatter only. Output maps are already zeroed by cudaMemsetAsync,
// so no zero-fill and no __syncthreads here: each thread scatters as soon
// as its own scan finishes.
__global__ __launch_bounds__(512)
void ipm_scan_kernel(const float* __restrict__ msm,
                     const int* __restrict__ refm,     // bool promoted to int32
                     const int* __restrict__ srcm,     // bool promoted to int32
                     float* __restrict__ out_score,
                     float* __restrict__ out_corr)     // bool output stored as float32
{
    const int p = blockIdx.x;
    const int tid = threadIdx.x;                  // 0..511

    const float* __restrict__ tile = msm + (size_t)p * RDIM * SDIM;
    float* __restrict__ oscore = out_score + (size_t)p * RDIM * SDIM;
    float* __restrict__ ocorr  = out_corr  + (size_t)p * RDIM * SDIM;

    // top-3 of RAW scores (exp is monotonic; exp applied to winners only)
    float b0 = -1e30f, b1 = -1e30f, b2 = -1e30f;
    int   j0 = 0,      j1 = 0,      j2 = 0;

    if (tid < 256) {
        // ---- column top-3 for column t = tid (scan r; coalesced across lanes)
        const int t = tid;
        #pragma unroll 8
        for (int r = 0; r < RDIM; ++r) {
            float v = tile[r * SDIM + t];
            if (v > b2) {                          // rare (~17/256 taken)
                if (v > b0)      { b2 = b1; j2 = j1; b1 = b0; j1 = j0; b0 = v; j0 = r; }
                else if (v > b1) { b2 = b1; j2 = j1; b1 = v;  j1 = r; }
                else             { b2 = v;  j2 = r; }
            }
        }
    } else {
        // ---- row top-3 for row t = tid-256 (contiguous float4 per thread)
        const int t = tid - 256;
        const float4* __restrict__ row = (const float4*)(tile + (size_t)t * SDIM);
        #pragma unroll 8
        for (int j = 0; j < SDIM / 4; ++j) {
            float4 q = row[j];
            float vals[4] = {q.x, q.y, q.z, q.w};
            #pragma unroll
            for (int u = 0; u < 4; ++u) {
                float v = vals[u];
                int s = j * 4 + u;
                if (v > b2) {
                    if (v > b0)      { b2 = b1; j2 = j1; b1 = b0; j1 = j0; b0 = v; j0 = s; }
                    else if (v > b1) { b2 = b1; j2 = j1; b1 = v;  j1 = s; }
                    else             { b2 = v;  j2 = s; }
                }
            }
        }
    }

    // ---------------- scatter (exp applied to the 3 winners only) ------------
    float vs[3] = {__expf(b0), __expf(b1), __expf(b2)};
    int   is[3] = {j0, j1, j2};

    if (tid < 256) {
        // Column t's top-3 along R
        const int t = tid;
        const bool ms = srcm[(size_t)p * SDIM + t] != 0;
        #pragma unroll
        for (int k = 0; k < 3; ++k) {
            int r = is[k];
            float v = vs[k];
            atomicAdd(&oscore[r * SDIM + t], 0.5f * v);
            if (v > 0.0f && ms && refm[(size_t)p * RDIM + r] != 0)
                ocorr[r * SDIM + t] = 1.0f;   // idempotent write, benign race
        }
    } else {
        // Row t's top-3 along S
        const int t = tid - 256;
        const bool mr = refm[(size_t)p * RDIM + t] != 0;
        #pragma unroll
        for (int k = 0; k < 3; ++k) {
            int s = is[k];
            float v = vs[k];
            atomicAdd(&oscore[t * SDIM + s], 0.5f * v);
            if (v > 0.0f && mr && srcm[(size_t)p * SDIM + s] != 0)
                ocorr[t * SDIM + s] = 1.0f;
        }
    }
}

extern "C" void kernel_launch(void* const* d_in, const int* in_sizes, int n_in,
                              void* d_out, int out_size)
{
    // metadata order: matching_score_map [P,R,S] f32, node_corr_scores [P] f32 (unused),
    //                 ref_knn_masks [P,R] bool->int32, src_knn_masks [P,S] bool->int32
    const float* msm  = (const float*)d_in[0];
    const int*   refm = (const int*)d_in[2];
    const int*   srcm = (const int*)d_in[3];

    const int P = in_sizes[1];                 // node_corr_scores has P elements
    float* out_score = (float*)d_out;
    float* out_corr  = out_score + (size_t)P * RDIM * SDIM;  // bool output as float32

    // Phase 1: zero both output maps at full write bandwidth (graph-capturable,
    // stream-ordered before the scan kernel).
    size_t total_bytes = (size_t)2 * P * RDIM * SDIM * sizeof(float);
    cudaMemsetAsync(d_out, 0, total_bytes, 0);

    // Phase 2: scan + scatter.
    ipm_scan_kernel<<<P, 512>>>(msm, refm, srcm, out_score, out_corr);
}